// round 7
// baseline (speedup 1.0000x reference)
#include <cuda_runtime.h>
#include <math.h>
#include <stdint.h>

#define NUM_SCALES 16
#define MAXP 524288u
#define HMASK (MAXP - 1u)
#define TPB 64

struct Cfg {
    float rx[NUM_SCALES], ry[NUM_SCALES], rz[NUM_SCALES], rt[NUM_SCALES];
    unsigned s1[NUM_SCALES], s2[NUM_SCALES], s3[NUM_SCALES];
    unsigned dense[NUM_SCALES];
    unsigned off2[NUM_SCALES];   // level offset in float2 units (16B-aligned: p % 8 == 0)
};

struct LvlBuf {
    float4 f4[8];     // aligned pair-words: entries {2m, 2m+1} containing corner 2j
    float2 fb[8];     // fallback load of corner 2j+1 when pair not adjacent
    float fx, fy, fz, ft;  // raw fracs; weights recomputed at consume (saves regs)
    unsigned masks;   // bits 0-7: corner 2j in high half; bits 8-15: pair adjacent
};

// Issue one level's gathers with maximum MLP:
// 8x LDG.128 (always) + 8x predicated LDG.64 (only non-adjacent lanes).
__device__ __forceinline__ void level_issue(
    const Cfg& cfg, int s, float4 p, const float2* __restrict__ tbl,
    LvlBuf& B)
{
    float px = p.x * cfg.rx[s];
    float py = p.y * cfg.ry[s];
    float pz = p.z * cfg.rz[s];
    float pt = p.w * cfg.rt[s];
    float gx = floorf(px), gy = floorf(py), gz = floorf(pz), gt = floorf(pt);
    B.fx = px - gx; B.fy = py - gy; B.fz = pz - gz; B.ft = pt - gt;
    unsigned ix = (unsigned)(int)gx, iy = (unsigned)(int)gy;
    unsigned iz = (unsigned)(int)gz, it = (unsigned)(int)gt;

    const float2* __restrict__ base = tbl + cfg.off2[s];
    const float4* __restrict__ base4 = (const float4*)base;

    unsigned a[8], b[8];
    if (cfg.dense[s]) {
        unsigned t1 = cfg.s1[s], t2 = cfg.s2[s], t3 = cfg.s3[s];
        unsigned b0 = ix + iy * t1 + iz * t2 + it * t3;
#pragma unroll
        for (int j = 0; j < 8; ++j) {
            unsigned byzt = b0 + ((j & 1) ? t1 : 0u) + ((j & 2) ? t2 : 0u) + ((j & 4) ? t3 : 0u);
            a[j] = byzt;          // x = ix corner
            b[j] = byzt + 1u;     // x = ix+1 corner
        }
    } else {
        unsigned hy0 = iy * 2654435761u, hy1 = (iy + 1u) * 2654435761u;
        unsigned hz0 = iz * 805459861u,  hz1 = (iz + 1u) * 805459861u;
        unsigned ht0 = it * 3674653429u, ht1 = (it + 1u) * 3674653429u;
#pragma unroll
        for (int j = 0; j < 8; ++j) {
            unsigned r = ((j & 1) ? hy1 : hy0) ^ ((j & 2) ? hz1 : hz0) ^ ((j & 4) ? ht1 : ht0);
            a[j] = (ix ^ r) & HMASK;
            b[j] = ((ix + 1u) ^ r) & HMASK;
        }
    }

    unsigned masks = 0u;
#pragma unroll
    for (int j = 0; j < 8; ++j) {
        B.f4[j] = __ldg(base4 + (a[j] >> 1));
        masks |= (a[j] & 1u) << j;
        masks |= ((a[j] ^ b[j]) == 1u ? 256u : 0u) << j;
    }
#pragma unroll
    for (int j = 0; j < 8; ++j) {
        if ((a[j] ^ b[j]) != 1u)
            B.fb[j] = __ldg(base + b[j]);   // predicated: only non-adjacent lanes
    }
    B.masks = masks;
}

__device__ __forceinline__ float2 level_consume(const LvlBuf& B)
{
    float fx = B.fx, fy = B.fy, fz = B.fz, ft = B.ft;
    float wx0 = 1.f - fx, wy0 = 1.f - fy, wz0 = 1.f - fz, wt0 = 1.f - ft;
    float wxy[4] = {wx0 * wy0, fx * wy0, wx0 * fy, fx * fy};
    float wzt[4] = {wz0 * wt0, fz * wt0, wz0 * ft, fz * ft};

    float o0 = 0.f, o1 = 0.f;
#pragma unroll
    for (int j = 0; j < 8; ++j) {
        bool hi  = (B.masks >> j) & 1u;
        bool adj = (B.masks >> (j + 8)) & 1u;
        float4 q = B.f4[j];
        float c0x = hi ? q.z : q.x, c0y = hi ? q.w : q.y;       // corner 2j
        float c1x = hi ? q.x : q.z, c1y = hi ? q.y : q.w;       // other half
        if (!adj) { c1x = B.fb[j].x; c1y = B.fb[j].y; }         // corner 2j+1 fallback
        float wz = wzt[j >> 1];
        float w0 = wxy[(j & 1) * 2]     * wz;
        float w1 = wxy[(j & 1) * 2 + 1] * wz;
        o0 = fmaf(w0, c0x, o0); o1 = fmaf(w0, c0y, o1);
        o0 = fmaf(w1, c1x, o0); o1 = fmaf(w1, c1y, o1);
    }
    return make_float2(o0, o1);
}

__global__ __launch_bounds__(TPB, 7) void henc_kernel(
    const float4* __restrict__ xyzt,
    const float2* __restrict__ tbl,
    float2* __restrict__ out2,
    Cfg cfg, int nq)
{
    __shared__ float2 sm2[TPB * 17];   // pitch 17 float2s -> conflict-light
    const int tid = threadIdx.x;
    const int q = blockIdx.x * TPB + tid;

    float4 p = (q < nq) ? xyzt[q] : make_float4(0.f, 0.f, 0.f, 0.f);

    LvlBuf A, B;

    // prologue: level 0 loads in flight before any consumption
    level_issue(cfg, 0, p, tbl, A);

#pragma unroll 1
    for (int s = 0; s < NUM_SCALES; s += 2) {
        level_issue(cfg, s + 1, p, tbl, B);   // level s+1 in flight
        sm2[tid * 17 + s] = level_consume(A);
        if (s + 2 < NUM_SCALES)
            level_issue(cfg, s + 2, p, tbl, A);  // level s+2 in flight
        sm2[tid * 17 + s + 1] = level_consume(B);
    }

    __syncthreads();

    // coalesced float2 tile store: block's rows are contiguous in gmem
    int base2 = blockIdx.x * (TPB * 16);
    int lim2 = nq * 16;
#pragma unroll
    for (int k = 0; k < 16; ++k) {
        int i = tid + k * TPB;
        int g = base2 + i;
        if (g < lim2) out2[g] = sm2[(i >> 4) * 17 + (i & 15)];
    }
}

extern "C" void kernel_launch(void* const* d_in, const int* in_sizes, int n_in,
                              void* d_out, int out_size)
{
    (void)n_in; (void)out_size;

    // Rebuild the reference's build_config() with the same float64 libm math.
    Cfg cfg;
    const double minr[4] = {16.0, 16.0, 16.0, 16.0};
    const double maxr[4] = {256.0, 256.0, 256.0, 128.0};
    double b[4];
    for (int d = 0; d < 4; ++d)
        b[d] = exp((log(maxr[d]) - log(minr[d])) / (double)(NUM_SCALES - 1));

    unsigned long long totalp = 0;
    for (int s = 0; s < NUM_SCALES; ++s) {
        long long res[4];
        for (int d = 0; d < 4; ++d)
            res[d] = (long long)ceil(minr[d] * pow(b[d], (double)s));
        long long raw = (res[0] + 1) * (res[1] + 1) * (res[2] + 1) * (res[3] + 1);
        long long pp = (raw % 8 == 0) ? raw : ((raw + 7) / 8) * 8;
        if (pp > (long long)MAXP) pp = (long long)MAXP;

        cfg.dense[s] = (raw <= pp) ? 1u : 0u;
        cfg.rx[s] = (float)res[0];
        cfg.ry[s] = (float)res[1];
        cfg.rz[s] = (float)res[2];
        cfg.rt[s] = (float)res[3];
        cfg.s1[s] = (unsigned)(res[0] + 1);
        cfg.s2[s] = (unsigned)((res[0] + 1) * (res[1] + 1));
        cfg.s3[s] = (unsigned)((res[0] + 1) * (res[1] + 1) * (res[2] + 1));
        cfg.off2[s] = (unsigned)totalp;
        totalp += (unsigned long long)pp;
    }

    int nq = in_sizes[0] / 4;
    const float4* xyzt = (const float4*)d_in[0];
    const float2* tbl  = (const float2*)d_in[1];
    float2* out2 = (float2*)d_out;

    int blocks = (nq + TPB - 1) / TPB;
    henc_kernel<<<blocks, TPB>>>(xyzt, tbl, out2, cfg, nq);
}

// round 8
// speedup vs baseline: 1.1292x; 1.1292x over previous
#include <cuda_runtime.h>
#include <math.h>
#include <stdint.h>

#define NUM_SCALES 16
#define MAXP 524288u
#define HMASK (MAXP - 1u)
#define TPB 128
#define NBINS 65536
#define MAXQ 1048576

struct Cfg {
    float rx[NUM_SCALES], ry[NUM_SCALES], rz[NUM_SCALES], rt[NUM_SCALES];
    unsigned s1[NUM_SCALES], s2[NUM_SCALES], s3[NUM_SCALES];
    unsigned dense[NUM_SCALES];
    unsigned off2[NUM_SCALES];   // level offset in float2 units (16B-aligned: p % 8 == 0)
};

// ---- scratch (static device globals; no allocation) ----
__device__ int g_cnt[NBINS];
__device__ int g_perm[MAXQ];

// ---- Morton key: 4 bits per dim interleaved -> 16-bit key ----
__device__ __forceinline__ unsigned spread4(unsigned v) {
    // v in [0,15]; bit b -> bit 4b
    return (v & 1u) | ((v & 2u) << 3) | ((v & 4u) << 6) | ((v & 8u) << 9);
}
__device__ __forceinline__ unsigned morton_key(float4 p) {
    unsigned kx = (unsigned)(p.x * 16.0f);
    unsigned ky = (unsigned)(p.y * 16.0f);
    unsigned kz = (unsigned)(p.z * 16.0f);
    unsigned kt = (unsigned)(p.w * 16.0f);
    kx = kx > 15u ? 15u : kx; ky = ky > 15u ? 15u : ky;
    kz = kz > 15u ? 15u : kz; kt = kt > 15u ? 15u : kt;
    return spread4(kx) | (spread4(ky) << 1) | (spread4(kz) << 2) | (spread4(kt) << 3);
}

__global__ void zero_cnt_kernel() {
    int i = blockIdx.x * blockDim.x + threadIdx.x;
    if (i < NBINS) g_cnt[i] = 0;
}

__global__ void hist_kernel(const float4* __restrict__ xyzt, int nq) {
    int i = blockIdx.x * blockDim.x + threadIdx.x;
    if (i < nq) atomicAdd(&g_cnt[morton_key(xyzt[i])], 1);
}

// single-block exclusive scan over NBINS counters (in place)
__global__ __launch_bounds__(1024) void scan_kernel() {
    __shared__ int sc[1024];
    int t = threadIdx.x;
    const int PER = NBINS / 1024;   // 64
    int base = t * PER;
    int sum = 0;
#pragma unroll 4
    for (int i = 0; i < PER; ++i) sum += g_cnt[base + i];
    sc[t] = sum;
    __syncthreads();
    // Hillis-Steele inclusive scan
    for (int off = 1; off < 1024; off <<= 1) {
        int v = (t >= off) ? sc[t - off] : 0;
        __syncthreads();
        sc[t] += v;
        __syncthreads();
    }
    int run = (t == 0) ? 0 : sc[t - 1];   // exclusive base for this thread
    for (int i = 0; i < PER; ++i) {
        int c = g_cnt[base + i];
        g_cnt[base + i] = run;
        run += c;
    }
}

__global__ void scatter_kernel(const float4* __restrict__ xyzt, int nq) {
    int i = blockIdx.x * blockDim.x + threadIdx.x;
    if (i < nq) {
        int pos = atomicAdd(&g_cnt[morton_key(xyzt[i])], 1);
        g_perm[pos] = i;
    }
}

// ---------------- main encode ----------------

struct LvlBuf {
    float4 f4[8];     // aligned pair-words: entries {2m, 2m+1} containing corner 2j
    float2 fb[8];     // fallback load of corner 2j+1 when pair not adjacent
    float fx, fy, fz, ft;
    unsigned masks;   // bits 0-7: corner 2j in high half; bits 8-15: pair adjacent
};

__device__ __forceinline__ void level_issue(
    const Cfg& cfg, int s, float4 p, const float2* __restrict__ tbl,
    LvlBuf& B)
{
    float px = p.x * cfg.rx[s];
    float py = p.y * cfg.ry[s];
    float pz = p.z * cfg.rz[s];
    float pt = p.w * cfg.rt[s];
    float gx = floorf(px), gy = floorf(py), gz = floorf(pz), gt = floorf(pt);
    B.fx = px - gx; B.fy = py - gy; B.fz = pz - gz; B.ft = pt - gt;
    unsigned ix = (unsigned)(int)gx, iy = (unsigned)(int)gy;
    unsigned iz = (unsigned)(int)gz, it = (unsigned)(int)gt;

    const float2* __restrict__ base = tbl + cfg.off2[s];
    const float4* __restrict__ base4 = (const float4*)base;

    unsigned a[8], b[8];
    if (cfg.dense[s]) {
        unsigned t1 = cfg.s1[s], t2 = cfg.s2[s], t3 = cfg.s3[s];
        unsigned b0 = ix + iy * t1 + iz * t2 + it * t3;
#pragma unroll
        for (int j = 0; j < 8; ++j) {
            unsigned byzt = b0 + ((j & 1) ? t1 : 0u) + ((j & 2) ? t2 : 0u) + ((j & 4) ? t3 : 0u);
            a[j] = byzt;
            b[j] = byzt + 1u;
        }
    } else {
        unsigned hy0 = iy * 2654435761u, hy1 = (iy + 1u) * 2654435761u;
        unsigned hz0 = iz * 805459861u,  hz1 = (iz + 1u) * 805459861u;
        unsigned ht0 = it * 3674653429u, ht1 = (it + 1u) * 3674653429u;
#pragma unroll
        for (int j = 0; j < 8; ++j) {
            unsigned r = ((j & 1) ? hy1 : hy0) ^ ((j & 2) ? hz1 : hz0) ^ ((j & 4) ? ht1 : ht0);
            a[j] = (ix ^ r) & HMASK;
            b[j] = ((ix + 1u) ^ r) & HMASK;
        }
    }

    unsigned masks = 0u;
#pragma unroll
    for (int j = 0; j < 8; ++j) {
        B.f4[j] = __ldg(base4 + (a[j] >> 1));
        masks |= (a[j] & 1u) << j;
        masks |= ((a[j] ^ b[j]) == 1u ? 256u : 0u) << j;
    }
#pragma unroll
    for (int j = 0; j < 8; ++j) {
        if ((a[j] ^ b[j]) != 1u)
            B.fb[j] = __ldg(base + b[j]);
    }
    B.masks = masks;
}

__device__ __forceinline__ float2 level_consume(const LvlBuf& B)
{
    float fx = B.fx, fy = B.fy, fz = B.fz, ft = B.ft;
    float wx0 = 1.f - fx, wy0 = 1.f - fy, wz0 = 1.f - fz, wt0 = 1.f - ft;
    float wxy[4] = {wx0 * wy0, fx * wy0, wx0 * fy, fx * fy};
    float wzt[4] = {wz0 * wt0, fz * wt0, wz0 * ft, fz * ft};

    float o0 = 0.f, o1 = 0.f;
#pragma unroll
    for (int j = 0; j < 8; ++j) {
        bool hi  = (B.masks >> j) & 1u;
        bool adj = (B.masks >> (j + 8)) & 1u;
        float4 q = B.f4[j];
        float c0x = hi ? q.z : q.x, c0y = hi ? q.w : q.y;
        float c1x = hi ? q.x : q.z, c1y = hi ? q.y : q.w;
        if (!adj) { c1x = B.fb[j].x; c1y = B.fb[j].y; }
        float wz = wzt[j >> 1];
        float w0 = wxy[(j & 1) * 2]     * wz;
        float w1 = wxy[(j & 1) * 2 + 1] * wz;
        o0 = fmaf(w0, c0x, o0); o1 = fmaf(w0, c0y, o1);
        o0 = fmaf(w1, c1x, o0); o1 = fmaf(w1, c1y, o1);
    }
    return make_float2(o0, o1);
}

__global__ __launch_bounds__(TPB, 3) void henc_kernel(
    const float4* __restrict__ xyzt,
    const float2* __restrict__ tbl,
    float2* __restrict__ out2,
    Cfg cfg, int nq)
{
    __shared__ float2 sm2[TPB * 17];
    __shared__ int qsh[TPB];
    const int tid = threadIdx.x;
    const int i = blockIdx.x * TPB + tid;

    int q = (i < nq) ? g_perm[i] : -1;
    qsh[tid] = q;
    float4 p = (q >= 0) ? xyzt[q] : make_float4(0.f, 0.f, 0.f, 0.f);

    LvlBuf A, B;
    level_issue(cfg, 0, p, tbl, A);

#pragma unroll 1
    for (int s = 0; s < NUM_SCALES; s += 2) {
        level_issue(cfg, s + 1, p, tbl, B);
        sm2[tid * 17 + s] = level_consume(A);
        if (s + 2 < NUM_SCALES)
            level_issue(cfg, s + 2, p, tbl, A);
        sm2[tid * 17 + s + 1] = level_consume(B);
    }

    __syncthreads();

    // scattered row store: 2 rows per warp-instruction (2 lines/wavefront)
#pragma unroll
    for (int k = 0; k < 16; ++k) {
        int m = tid + k * TPB;
        int row = m >> 4, chunk = m & 15;
        int qr = qsh[row];
        if (qr >= 0) out2[qr * 16 + chunk] = sm2[row * 17 + chunk];
    }
}

extern "C" void kernel_launch(void* const* d_in, const int* in_sizes, int n_in,
                              void* d_out, int out_size)
{
    (void)n_in; (void)out_size;

    // Rebuild the reference's build_config() with the same float64 libm math.
    Cfg cfg;
    const double minr[4] = {16.0, 16.0, 16.0, 16.0};
    const double maxr[4] = {256.0, 256.0, 256.0, 128.0};
    double b[4];
    for (int d = 0; d < 4; ++d)
        b[d] = exp((log(maxr[d]) - log(minr[d])) / (double)(NUM_SCALES - 1));

    unsigned long long totalp = 0;
    for (int s = 0; s < NUM_SCALES; ++s) {
        long long res[4];
        for (int d = 0; d < 4; ++d)
            res[d] = (long long)ceil(minr[d] * pow(b[d], (double)s));
        long long raw = (res[0] + 1) * (res[1] + 1) * (res[2] + 1) * (res[3] + 1);
        long long pp = (raw % 8 == 0) ? raw : ((raw + 7) / 8) * 8;
        if (pp > (long long)MAXP) pp = (long long)MAXP;

        cfg.dense[s] = (raw <= pp) ? 1u : 0u;
        cfg.rx[s] = (float)res[0];
        cfg.ry[s] = (float)res[1];
        cfg.rz[s] = (float)res[2];
        cfg.rt[s] = (float)res[3];
        cfg.s1[s] = (unsigned)(res[0] + 1);
        cfg.s2[s] = (unsigned)((res[0] + 1) * (res[1] + 1));
        cfg.s3[s] = (unsigned)((res[0] + 1) * (res[1] + 1) * (res[2] + 1));
        cfg.off2[s] = (unsigned)totalp;
        totalp += (unsigned long long)pp;
    }

    int nq = in_sizes[0] / 4;
    const float4* xyzt = (const float4*)d_in[0];
    const float2* tbl  = (const float2*)d_in[1];
    float2* out2 = (float2*)d_out;

    // 1) Morton binning (counting sort) for warp-level gather locality
    zero_cnt_kernel<<<(NBINS + 255) / 256, 256>>>();
    hist_kernel<<<(nq + 255) / 256, 256>>>(xyzt, nq);
    scan_kernel<<<1, 1024>>>();
    scatter_kernel<<<(nq + 255) / 256, 256>>>(xyzt, nq);

    // 2) encode in sorted order
    int blocks = (nq + TPB - 1) / TPB;
    henc_kernel<<<blocks, TPB>>>(xyzt, tbl, out2, cfg, nq);
}

// round 10
// speedup vs baseline: 1.3636x; 1.2076x over previous
#include <cuda_runtime.h>
#include <math.h>
#include <stdint.h>

#define NUM_SCALES 16
#define MAXP 524288u
#define HMASK (MAXP - 1u)
#define TPB 128
#define NBINS 65536
#define MAXQ 1048576

struct Cfg {
    float rx[NUM_SCALES], ry[NUM_SCALES], rz[NUM_SCALES], rt[NUM_SCALES];
    unsigned s1[NUM_SCALES], s2[NUM_SCALES], s3[NUM_SCALES];
    unsigned dense[NUM_SCALES];
    unsigned off2[NUM_SCALES];   // level offset in float2 units (16B-aligned: p % 8 == 0)
};

// ---- scratch (static device globals; no allocation) ----
__device__ int g_cnt[NBINS];
__device__ int g_bsum[256];
__device__ unsigned short g_key[MAXQ];
__device__ int g_perm[MAXQ];

// ---- Morton key: 4 bits per dim interleaved -> 16-bit key ----
__device__ __forceinline__ unsigned spread4(unsigned v) {
    return (v & 1u) | ((v & 2u) << 3) | ((v & 4u) << 6) | ((v & 8u) << 9);
}
__device__ __forceinline__ unsigned morton_key(float4 p) {
    unsigned kx = (unsigned)(p.x * 16.0f);
    unsigned ky = (unsigned)(p.y * 16.0f);
    unsigned kz = (unsigned)(p.z * 16.0f);
    unsigned kt = (unsigned)(p.w * 16.0f);
    kx = kx > 15u ? 15u : kx; ky = ky > 15u ? 15u : ky;
    kz = kz > 15u ? 15u : kz; kt = kt > 15u ? 15u : kt;
    return spread4(kx) | (spread4(ky) << 1) | (spread4(kz) << 2) | (spread4(kt) << 3);
}

__global__ void zero_cnt_kernel() {   // 64 blocks x 256 threads, int4 stores
    int i = blockIdx.x * blockDim.x + threadIdx.x;
    ((int4*)g_cnt)[i] = make_int4(0, 0, 0, 0);
}

// histogram + cache 16-bit key (avoids re-reading 16MB xyzt in scatter)
__global__ void hist_kernel(const float4* __restrict__ xyzt, int nq) {
    int i = blockIdx.x * blockDim.x + threadIdx.x;
    if (i < nq) {
        unsigned k = morton_key(xyzt[i]);
        g_key[i] = (unsigned short)k;
        atomicAdd(&g_cnt[k], 1);
    }
}

// 3-phase multi-block exclusive scan over NBINS counters (in place)
__global__ __launch_bounds__(256) void scan_p1() {     // 256 blocks: partial sums
    __shared__ int sc[256];
    int t = threadIdx.x;
    int i = blockIdx.x * 256 + t;
    sc[t] = g_cnt[i];
    __syncthreads();
#pragma unroll
    for (int off = 128; off > 0; off >>= 1) {
        if (t < off) sc[t] += sc[t + off];
        __syncthreads();
    }
    if (t == 0) g_bsum[blockIdx.x] = sc[0];
}

__global__ __launch_bounds__(256) void scan_p2() {     // 1 block: scan partials
    __shared__ int sc[256];
    int t = threadIdx.x;
    sc[t] = g_bsum[t];
    __syncthreads();
    for (int off = 1; off < 256; off <<= 1) {
        int v = (t >= off) ? sc[t - off] : 0;
        __syncthreads();
        sc[t] += v;
        __syncthreads();
    }
    g_bsum[t] = (t == 0) ? 0 : sc[t - 1];   // exclusive
}

__global__ __launch_bounds__(256) void scan_p3() {     // 256 blocks: local scan + base
    __shared__ int sc[256];
    int t = threadIdx.x;
    int i = blockIdx.x * 256 + t;
    int c = g_cnt[i];
    sc[t] = c;
    __syncthreads();
    for (int off = 1; off < 256; off <<= 1) {
        int v = (t >= off) ? sc[t - off] : 0;
        __syncthreads();
        sc[t] += v;
        __syncthreads();
    }
    g_cnt[i] = g_bsum[blockIdx.x] + sc[t] - c;  // exclusive prefix + block base
}

__global__ void scatter_kernel(int nq) {
    int i = blockIdx.x * blockDim.x + threadIdx.x;
    if (i < nq) {
        int pos = atomicAdd(&g_cnt[(unsigned)g_key[i]], 1);
        g_perm[pos] = i;
    }
}

// ---------------- main encode ----------------

struct LvlBuf {
    float4 f4[8];     // aligned pair-words: entries {2m, 2m+1} containing corner 2j
    float2 fb[8];     // fallback load of corner 2j+1 when pair not adjacent
    float fx, fy, fz, ft;
    unsigned masks;   // bits 0-7: corner 2j in high half; bits 8-15: pair adjacent
};

__device__ __forceinline__ void level_issue(
    const Cfg& cfg, int s, float4 p, const float2* __restrict__ tbl,
    LvlBuf& B)
{
    float px = p.x * cfg.rx[s];
    float py = p.y * cfg.ry[s];
    float pz = p.z * cfg.rz[s];
    float pt = p.w * cfg.rt[s];
    float gx = floorf(px), gy = floorf(py), gz = floorf(pz), gt = floorf(pt);
    B.fx = px - gx; B.fy = py - gy; B.fz = pz - gz; B.ft = pt - gt;
    unsigned ix = (unsigned)(int)gx, iy = (unsigned)(int)gy;
    unsigned iz = (unsigned)(int)gz, it = (unsigned)(int)gt;

    const float2* __restrict__ base = tbl + cfg.off2[s];
    const float4* __restrict__ base4 = (const float4*)base;

    unsigned a[8], b[8];
    if (cfg.dense[s]) {
        unsigned t1 = cfg.s1[s], t2 = cfg.s2[s], t3 = cfg.s3[s];
        unsigned b0 = ix + iy * t1 + iz * t2 + it * t3;
#pragma unroll
        for (int j = 0; j < 8; ++j) {
            unsigned byzt = b0 + ((j & 1) ? t1 : 0u) + ((j & 2) ? t2 : 0u) + ((j & 4) ? t3 : 0u);
            a[j] = byzt;
            b[j] = byzt + 1u;
        }
    } else {
        unsigned hy0 = iy * 2654435761u, hy1 = (iy + 1u) * 2654435761u;
        unsigned hz0 = iz * 805459861u,  hz1 = (iz + 1u) * 805459861u;
        unsigned ht0 = it * 3674653429u, ht1 = (it + 1u) * 3674653429u;
#pragma unroll
        for (int j = 0; j < 8; ++j) {
            unsigned r = ((j & 1) ? hy1 : hy0) ^ ((j & 2) ? hz1 : hz0) ^ ((j & 4) ? ht1 : ht0);
            a[j] = (ix ^ r) & HMASK;
            b[j] = ((ix + 1u) ^ r) & HMASK;
        }
    }

    unsigned masks = 0u;
#pragma unroll
    for (int j = 0; j < 8; ++j) {
        B.f4[j] = __ldg(base4 + (a[j] >> 1));
        masks |= (a[j] & 1u) << j;
        masks |= ((a[j] ^ b[j]) == 1u ? 256u : 0u) << j;
    }
#pragma unroll
    for (int j = 0; j < 8; ++j) {
        if ((a[j] ^ b[j]) != 1u)
            B.fb[j] = __ldg(base + b[j]);
    }
    B.masks = masks;
}

__device__ __forceinline__ float2 level_consume(const LvlBuf& B)
{
    float fx = B.fx, fy = B.fy, fz = B.fz, ft = B.ft;
    float wx0 = 1.f - fx, wy0 = 1.f - fy, wz0 = 1.f - fz, wt0 = 1.f - ft;
    float wxy[4] = {wx0 * wy0, fx * wy0, wx0 * fy, fx * fy};
    float wzt[4] = {wz0 * wt0, fz * wt0, wz0 * ft, fz * ft};

    float o0 = 0.f, o1 = 0.f;
#pragma unroll
    for (int j = 0; j < 8; ++j) {
        bool hi  = (B.masks >> j) & 1u;
        bool adj = (B.masks >> (j + 8)) & 1u;
        float4 q = B.f4[j];
        float c0x = hi ? q.z : q.x, c0y = hi ? q.w : q.y;
        float c1x = hi ? q.x : q.z, c1y = hi ? q.y : q.w;
        if (!adj) { c1x = B.fb[j].x; c1y = B.fb[j].y; }
        float wz = wzt[j >> 1];
        float w0 = wxy[(j & 1) * 2]     * wz;
        float w1 = wxy[(j & 1) * 2 + 1] * wz;
        o0 = fmaf(w0, c0x, o0); o1 = fmaf(w0, c0y, o1);
        o0 = fmaf(w1, c1x, o0); o1 = fmaf(w1, c1y, o1);
    }
    return make_float2(o0, o1);
}

__global__ __launch_bounds__(TPB, 3) void henc_kernel(
    const float4* __restrict__ xyzt,
    const float2* __restrict__ tbl,
    float2* __restrict__ out2,
    Cfg cfg, int nq)
{
    __shared__ float2 sm2[TPB * 17];
    __shared__ int qsh[TPB];
    const int tid = threadIdx.x;
    const int i = blockIdx.x * TPB + tid;

    int q = (i < nq) ? g_perm[i] : -1;
    qsh[tid] = q;
    float4 p = (q >= 0) ? __ldg(&xyzt[q]) : make_float4(0.f, 0.f, 0.f, 0.f);

    LvlBuf A, B;
    level_issue(cfg, 0, p, tbl, A);

#pragma unroll 1
    for (int s = 0; s < NUM_SCALES; s += 2) {
        level_issue(cfg, s + 1, p, tbl, B);
        sm2[tid * 17 + s] = level_consume(A);
        if (s + 2 < NUM_SCALES)
            level_issue(cfg, s + 2, p, tbl, A);
        sm2[tid * 17 + s + 1] = level_consume(B);
    }

    __syncthreads();

    // scattered row store: 2 rows per warp-instruction (2 lines/wavefront)
#pragma unroll
    for (int k = 0; k < 16; ++k) {
        int m = tid + k * TPB;
        int row = m >> 4, chunk = m & 15;
        int qr = qsh[row];
        if (qr >= 0) out2[qr * 16 + chunk] = sm2[row * 17 + chunk];
    }
}

extern "C" void kernel_launch(void* const* d_in, const int* in_sizes, int n_in,
                              void* d_out, int out_size)
{
    (void)n_in; (void)out_size;

    // Rebuild the reference's build_config() with the same float64 libm math.
    Cfg cfg;
    const double minr[4] = {16.0, 16.0, 16.0, 16.0};
    const double maxr[4] = {256.0, 256.0, 256.0, 128.0};
    double b[4];
    for (int d = 0; d < 4; ++d)
        b[d] = exp((log(maxr[d]) - log(minr[d])) / (double)(NUM_SCALES - 1));

    unsigned long long totalp = 0;
    for (int s = 0; s < NUM_SCALES; ++s) {
        long long res[4];
        for (int d = 0; d < 4; ++d)
            res[d] = (long long)ceil(minr[d] * pow(b[d], (double)s));
        long long raw = (res[0] + 1) * (res[1] + 1) * (res[2] + 1) * (res[3] + 1);
        long long pp = (raw % 8 == 0) ? raw : ((raw + 7) / 8) * 8;
        if (pp > (long long)MAXP) pp = (long long)MAXP;

        cfg.dense[s] = (raw <= pp) ? 1u : 0u;
        cfg.rx[s] = (float)res[0];
        cfg.ry[s] = (float)res[1];
        cfg.rz[s] = (float)res[2];
        cfg.rt[s] = (float)res[3];
        cfg.s1[s] = (unsigned)(res[0] + 1);
        cfg.s2[s] = (unsigned)((res[0] + 1) * (res[1] + 1));
        cfg.s3[s] = (unsigned)((res[0] + 1) * (res[1] + 1) * (res[2] + 1));
        cfg.off2[s] = (unsigned)totalp;
        totalp += (unsigned long long)pp;
    }

    int nq = in_sizes[0] / 4;
    const float4* xyzt = (const float4*)d_in[0];
    const float2* tbl  = (const float2*)d_in[1];
    float2* out2 = (float2*)d_out;

    // 1) Morton binning (counting sort) for warp-level gather locality
    zero_cnt_kernel<<<NBINS / (256 * 4), 256>>>();
    hist_kernel<<<(nq + 255) / 256, 256>>>(xyzt, nq);
    scan_p1<<<256, 256>>>();
    scan_p2<<<1, 256>>>();
    scan_p3<<<256, 256>>>();
    scatter_kernel<<<(nq + 255) / 256, 256>>>(nq);

    // 2) encode in sorted order
    int blocks = (nq + TPB - 1) / TPB;
    henc_kernel<<<blocks, TPB>>>(xyzt, tbl, out2, cfg, nq);
}

// round 11
// speedup vs baseline: 1.3876x; 1.0175x over previous
#include <cuda_runtime.h>
#include <math.h>
#include <stdint.h>

#define NUM_SCALES 16
#define MAXP 524288u
#define HMASK (MAXP - 1u)
#define TPB 128
#define NBINS (1 << 20)
#define MAXQ 1048576

struct Cfg {
    float rx[NUM_SCALES], ry[NUM_SCALES], rz[NUM_SCALES], rt[NUM_SCALES];
    unsigned s1[NUM_SCALES], s2[NUM_SCALES], s3[NUM_SCALES];
    unsigned dense[NUM_SCALES];
    unsigned off2[NUM_SCALES];   // level offset in float2 units (16B-aligned: p % 8 == 0)
};

// ---- scratch (static device globals; no allocation) ----
__device__ int g_cnt[NBINS];
__device__ int g_bsum[1024];
__device__ unsigned g_key[MAXQ];
__device__ int g_perm[MAXQ];

// ---- Morton key: 5 bits per dim interleaved -> 20-bit key ----
__device__ __forceinline__ unsigned spread5(unsigned v) {
    return (v & 1u) | ((v & 2u) << 3) | ((v & 4u) << 6) | ((v & 8u) << 9) | ((v & 16u) << 12);
}
__device__ __forceinline__ unsigned morton_key(float4 p) {
    unsigned kx = (unsigned)(p.x * 32.0f);
    unsigned ky = (unsigned)(p.y * 32.0f);
    unsigned kz = (unsigned)(p.z * 32.0f);
    unsigned kt = (unsigned)(p.w * 32.0f);
    kx = kx > 31u ? 31u : kx; ky = ky > 31u ? 31u : ky;
    kz = kz > 31u ? 31u : kz; kt = kt > 31u ? 31u : kt;
    return spread5(kx) | (spread5(ky) << 1) | (spread5(kz) << 2) | (spread5(kt) << 3);
}

__global__ void zero_cnt_kernel() {   // NBINS/1024 blocks x 256 threads, int4 stores
    int i = blockIdx.x * blockDim.x + threadIdx.x;
    ((int4*)g_cnt)[i] = make_int4(0, 0, 0, 0);
}

// histogram + cache 20-bit key (avoids re-reading 16MB xyzt in scatter)
__global__ void hist_kernel(const float4* __restrict__ xyzt, int nq) {
    int i = blockIdx.x * blockDim.x + threadIdx.x;
    if (i < nq) {
        unsigned k = morton_key(xyzt[i]);
        g_key[i] = k;
        atomicAdd(&g_cnt[k], 1);
    }
}

// 3-phase multi-block exclusive scan over NBINS counters (in place).
// Each of 1024 tiles covers 1024 bins (256 threads x 4 bins via int4).
__global__ __launch_bounds__(256) void scan_p1() {     // 1024 blocks: tile sums
    __shared__ int sc[256];
    int t = threadIdx.x;
    int4 v = ((const int4*)g_cnt)[blockIdx.x * 256 + t];
    sc[t] = v.x + v.y + v.z + v.w;
    __syncthreads();
#pragma unroll
    for (int off = 128; off > 0; off >>= 1) {
        if (t < off) sc[t] += sc[t + off];
        __syncthreads();
    }
    if (t == 0) g_bsum[blockIdx.x] = sc[0];
}

__global__ __launch_bounds__(1024) void scan_p2() {    // 1 block: scan 1024 partials
    __shared__ int sc[1024];
    int t = threadIdx.x;
    sc[t] = g_bsum[t];
    __syncthreads();
    for (int off = 1; off < 1024; off <<= 1) {
        int v = (t >= off) ? sc[t - off] : 0;
        __syncthreads();
        sc[t] += v;
        __syncthreads();
    }
    g_bsum[t] = (t == 0) ? 0 : sc[t - 1];   // exclusive
}

__global__ __launch_bounds__(256) void scan_p3() {     // 1024 blocks: local scan + base
    __shared__ int sc[256];
    int t = threadIdx.x;
    int gi = blockIdx.x * 256 + t;
    int4 v = ((const int4*)g_cnt)[gi];
    int tsum = v.x + v.y + v.z + v.w;
    sc[t] = tsum;
    __syncthreads();
    for (int off = 1; off < 256; off <<= 1) {
        int u = (t >= off) ? sc[t - off] : 0;
        __syncthreads();
        sc[t] += u;
        __syncthreads();
    }
    int base = g_bsum[blockIdx.x] + sc[t] - tsum;  // exclusive prefix for thread's 4 bins
    int4 o;
    o.x = base;
    o.y = base + v.x;
    o.z = base + v.x + v.y;
    o.w = base + v.x + v.y + v.z;
    ((int4*)g_cnt)[gi] = o;
}

__global__ void scatter_kernel(int nq) {
    int i = blockIdx.x * blockDim.x + threadIdx.x;
    if (i < nq) {
        int pos = atomicAdd(&g_cnt[g_key[i]], 1);
        g_perm[pos] = i;
    }
}

// ---------------- main encode ----------------

struct LvlBuf {
    float4 f4[8];     // aligned pair-words: entries {2m, 2m+1} containing corner 2j
    float2 fb[8];     // fallback load of corner 2j+1 when pair not adjacent
    float fx, fy, fz, ft;
    unsigned masks;   // bits 0-7: corner 2j in high half; bits 8-15: pair adjacent
};

__device__ __forceinline__ void level_issue(
    const Cfg& cfg, int s, float4 p, const float2* __restrict__ tbl,
    LvlBuf& B)
{
    float px = p.x * cfg.rx[s];
    float py = p.y * cfg.ry[s];
    float pz = p.z * cfg.rz[s];
    float pt = p.w * cfg.rt[s];
    float gx = floorf(px), gy = floorf(py), gz = floorf(pz), gt = floorf(pt);
    B.fx = px - gx; B.fy = py - gy; B.fz = pz - gz; B.ft = pt - gt;
    unsigned ix = (unsigned)(int)gx, iy = (unsigned)(int)gy;
    unsigned iz = (unsigned)(int)gz, it = (unsigned)(int)gt;

    const float2* __restrict__ base = tbl + cfg.off2[s];
    const float4* __restrict__ base4 = (const float4*)base;

    unsigned a[8], b[8];
    if (cfg.dense[s]) {
        unsigned t1 = cfg.s1[s], t2 = cfg.s2[s], t3 = cfg.s3[s];
        unsigned b0 = ix + iy * t1 + iz * t2 + it * t3;
#pragma unroll
        for (int j = 0; j < 8; ++j) {
            unsigned byzt = b0 + ((j & 1) ? t1 : 0u) + ((j & 2) ? t2 : 0u) + ((j & 4) ? t3 : 0u);
            a[j] = byzt;
            b[j] = byzt + 1u;
        }
    } else {
        unsigned hy0 = iy * 2654435761u, hy1 = (iy + 1u) * 2654435761u;
        unsigned hz0 = iz * 805459861u,  hz1 = (iz + 1u) * 805459861u;
        unsigned ht0 = it * 3674653429u, ht1 = (it + 1u) * 3674653429u;
#pragma unroll
        for (int j = 0; j < 8; ++j) {
            unsigned r = ((j & 1) ? hy1 : hy0) ^ ((j & 2) ? hz1 : hz0) ^ ((j & 4) ? ht1 : ht0);
            a[j] = (ix ^ r) & HMASK;
            b[j] = ((ix + 1u) ^ r) & HMASK;
        }
    }

    unsigned masks = 0u;
#pragma unroll
    for (int j = 0; j < 8; ++j) {
        B.f4[j] = __ldg(base4 + (a[j] >> 1));
        masks |= (a[j] & 1u) << j;
        masks |= ((a[j] ^ b[j]) == 1u ? 256u : 0u) << j;
    }
#pragma unroll
    for (int j = 0; j < 8; ++j) {
        if ((a[j] ^ b[j]) != 1u)
            B.fb[j] = __ldg(base + b[j]);
    }
    B.masks = masks;
}

__device__ __forceinline__ float2 level_consume(const LvlBuf& B)
{
    float fx = B.fx, fy = B.fy, fz = B.fz, ft = B.ft;
    float wx0 = 1.f - fx, wy0 = 1.f - fy, wz0 = 1.f - fz, wt0 = 1.f - ft;
    float wxy[4] = {wx0 * wy0, fx * wy0, wx0 * fy, fx * fy};
    float wzt[4] = {wz0 * wt0, fz * wt0, wz0 * ft, fz * ft};

    float o0 = 0.f, o1 = 0.f;
#pragma unroll
    for (int j = 0; j < 8; ++j) {
        bool hi  = (B.masks >> j) & 1u;
        bool adj = (B.masks >> (j + 8)) & 1u;
        float4 q = B.f4[j];
        float c0x = hi ? q.z : q.x, c0y = hi ? q.w : q.y;
        float c1x = hi ? q.x : q.z, c1y = hi ? q.y : q.w;
        if (!adj) { c1x = B.fb[j].x; c1y = B.fb[j].y; }
        float wz = wzt[j >> 1];
        float w0 = wxy[(j & 1) * 2]     * wz;
        float w1 = wxy[(j & 1) * 2 + 1] * wz;
        o0 = fmaf(w0, c0x, o0); o1 = fmaf(w0, c0y, o1);
        o0 = fmaf(w1, c1x, o0); o1 = fmaf(w1, c1y, o1);
    }
    return make_float2(o0, o1);
}

__global__ __launch_bounds__(TPB, 3) void henc_kernel(
    const float4* __restrict__ xyzt,
    const float2* __restrict__ tbl,
    float2* __restrict__ out2,
    Cfg cfg, int nq)
{
    __shared__ float2 sm2[TPB * 17];
    __shared__ int qsh[TPB];
    const int tid = threadIdx.x;
    const int i = blockIdx.x * TPB + tid;

    int q = (i < nq) ? g_perm[i] : -1;
    qsh[tid] = q;
    float4 p = (q >= 0) ? __ldg(&xyzt[q]) : make_float4(0.f, 0.f, 0.f, 0.f);

    LvlBuf A, B;
    level_issue(cfg, 0, p, tbl, A);

#pragma unroll 1
    for (int s = 0; s < NUM_SCALES; s += 2) {
        level_issue(cfg, s + 1, p, tbl, B);
        sm2[tid * 17 + s] = level_consume(A);
        if (s + 2 < NUM_SCALES)
            level_issue(cfg, s + 2, p, tbl, A);
        sm2[tid * 17 + s + 1] = level_consume(B);
    }

    __syncthreads();

    // scattered row store: 2 rows per warp-instruction (2 lines/wavefront)
#pragma unroll
    for (int k = 0; k < 16; ++k) {
        int m = tid + k * TPB;
        int row = m >> 4, chunk = m & 15;
        int qr = qsh[row];
        if (qr >= 0) out2[qr * 16 + chunk] = sm2[row * 17 + chunk];
    }
}

extern "C" void kernel_launch(void* const* d_in, const int* in_sizes, int n_in,
                              void* d_out, int out_size)
{
    (void)n_in; (void)out_size;

    // Rebuild the reference's build_config() with the same float64 libm math.
    Cfg cfg;
    const double minr[4] = {16.0, 16.0, 16.0, 16.0};
    const double maxr[4] = {256.0, 256.0, 256.0, 128.0};
    double b[4];
    for (int d = 0; d < 4; ++d)
        b[d] = exp((log(maxr[d]) - log(minr[d])) / (double)(NUM_SCALES - 1));

    unsigned long long totalp = 0;
    for (int s = 0; s < NUM_SCALES; ++s) {
        long long res[4];
        for (int d = 0; d < 4; ++d)
            res[d] = (long long)ceil(minr[d] * pow(b[d], (double)s));
        long long raw = (res[0] + 1) * (res[1] + 1) * (res[2] + 1) * (res[3] + 1);
        long long pp = (raw % 8 == 0) ? raw : ((raw + 7) / 8) * 8;
        if (pp > (long long)MAXP) pp = (long long)MAXP;

        cfg.dense[s] = (raw <= pp) ? 1u : 0u;
        cfg.rx[s] = (float)res[0];
        cfg.ry[s] = (float)res[1];
        cfg.rz[s] = (float)res[2];
        cfg.rt[s] = (float)res[3];
        cfg.s1[s] = (unsigned)(res[0] + 1);
        cfg.s2[s] = (unsigned)((res[0] + 1) * (res[1] + 1));
        cfg.s3[s] = (unsigned)((res[0] + 1) * (res[1] + 1) * (res[2] + 1));
        cfg.off2[s] = (unsigned)totalp;
        totalp += (unsigned long long)pp;
    }

    int nq = in_sizes[0] / 4;
    const float4* xyzt = (const float4*)d_in[0];
    const float2* tbl  = (const float2*)d_in[1];
    float2* out2 = (float2*)d_out;

    // 1) Morton binning (counting sort, 2^20 bins) for warp-level gather locality
    zero_cnt_kernel<<<NBINS / (256 * 4), 256>>>();
    hist_kernel<<<(nq + 255) / 256, 256>>>(xyzt, nq);
    scan_p1<<<1024, 256>>>();
    scan_p2<<<1, 1024>>>();
    scan_p3<<<1024, 256>>>();
    scatter_kernel<<<(nq + 255) / 256, 256>>>(nq);

    // 2) encode in sorted order
    int blocks = (nq + TPB - 1) / TPB;
    henc_kernel<<<blocks, TPB>>>(xyzt, tbl, out2, cfg, nq);
}